// round 13
// baseline (speedup 1.0000x reference)
#include <cuda_runtime.h>
#include <cuda_bf16.h>

// ANFIS fuzzy inference, batch=2M rows x 4 features. SINGLE kernel launch.
// out = sum_j(w_j * clip(conseq_j)) / max(sum_j w_j, 1e-8),
// w_j = prod of 4 Gaussian memberships.
//
// Constant prep folded into the main kernel (no second graph node):
//  - block 0 computes a' = (1/sigma)*sqrt(0.5*log2 e), b' = -c*a',
//    cq = clip(conseq,0,100) into a __device__ global blob (vector layout:
//    ab[11] float2 pairs; cqp[32] permuted into group consumption order),
//    then fence + st.release flag.
//  - all other blocks prefetch their x rows (independent), then spin on
//    ld.acquire of the flag (only wave-1 blocks ever wait).
//  - last-finishing block resets flag/counter so graph replays start clean.
//  - body consumes constants via per-use global loads (L1 broadcast hits,
//    transient registers — same economics as the validated cbank body).
//
// Row math (validated across R9-R12):
//  - mu_i = ex2((-d)*d), d = x*a'+b' (negation folded into FMUL operand).
//  - pair-product CSE: P[9] = mu[0..2] x mu[3..5], Q[6] = mu[6..8] x mu[9..10].
//  - group factorization over the 6 shared Q factors; split accumulators;
//    CSE'd unweighted group sums.
//  - 2 rows/thread, 256 threads.

namespace {
// Rules grouped by q = (ante2-6)*2 + (ante3-9); p = ante0*3 + (ante1-3).
// Verified against RULE_ANTECEDENTS.
//   group extents: g0: m 0-6, g1: 7-10, g2: 11-15, g3: 16-20, g4: 21-25, g5: 26-29
__device__ constexpr int GRP_P[30]  = {0,3,1,2,8,5,7,  8,7,5,4,  0,4,3,6,5,
                                       0,1,3,2,8,  0,1,3,2,7,  0,1,3,4};
__device__ constexpr int GRP_CQ[30] = {9,13,15,19,23,27,28,  22,24,25,29,
                                       2,11,17,18,20,  4,10,12,14,26,
                                       0,3,6,7,21,  1,5,8,16};
// m -> group index (from offsets {0,7,11,16,21,26,30})
__device__ constexpr int GRP_OF[30] = {0,0,0,0,0,0,0, 1,1,1,1, 2,2,2,2,2,
                                       3,3,3,3,3, 4,4,4,4,4, 5,5,5,5};
__device__ constexpr int DM[11] = {0,0,0,1,1,1,2,2,2,3,3};
}

// Device-global constant blob + publish flag + replay-reset counter.
struct CstBlob {
    float  cqp[32];    // permuted clipped conseq (padded) -> float4 x8
    float2 ab[11];     // (a', b') interleaved -> 64-bit loads
};
__device__ __align__(16) CstBlob g_blob;
__device__ int      g_flag = 0;
__device__ unsigned g_done = 0;

__device__ __forceinline__ float ex2(float t) {
    float r; asm("ex2.approx.ftz.f32 %0, %1;" : "=f"(r) : "f"(t)); return r;
}

constexpr int THREADS = 256;
constexpr int ROWS_PER_THREAD = 2;
constexpr int TILE = THREADS * ROWS_PER_THREAD;   // 512 rows/block

__device__ __forceinline__ float anfis_row(const float4 xv)
{
    const float xd[4] = {xv.x, xv.y, xv.z, xv.w};

    // 11 memberships: 64-bit const load + FFMA + FMUL(neg-src) + MUFU each.
    float mu[11];
    #pragma unroll
    for (int i = 0; i < 11; i++) {
        float2 ab = g_blob.ab[i];
        float d = fmaf(xd[DM[i]], ab.x, ab.y);
        mu[i] = ex2(-d * d);
    }

    // Pair products.
    float Pv[9], Qv[6];
    #pragma unroll
    for (int i = 0; i < 3; i++)
        #pragma unroll
        for (int j = 0; j < 3; j++)
            Pv[i * 3 + j] = mu[i] * mu[3 + j];
    #pragma unroll
    for (int i = 0; i < 3; i++)
        #pragma unroll
        for (int j = 0; j < 2; j++)
            Qv[i * 2 + j] = mu[6 + i] * mu[9 + j];

    // Weighted group inner sums: cq streamed as 8 x 128-bit loads, permuted.
    float s1[6];
    #pragma unroll
    for (int g = 0; g < 6; g++) s1[g] = 0.0f;

    const float4* cq4 = (const float4*)g_blob.cqp;
    #pragma unroll
    for (int chunk = 0; chunk < 8; chunk++) {
        float4 C = cq4[chunk];
        const float cv[4] = {C.x, C.y, C.z, C.w};
        #pragma unroll
        for (int e = 0; e < 4; e++) {
            const int m = chunk * 4 + e;
            if (m < 30) {
                s1[GRP_OF[m]] = fmaf(Pv[GRP_P[m]], cv[e], s1[GRP_OF[m]]);
            }
        }
    }

    // Unweighted group sums with CSE (16 ADDs).
    float u = (Pv[0] + Pv[1]) + Pv[3];   // {0,1,3}
    float v = u + Pv[2];                 // {0,1,2,3}
    float s0_0 = v + ((Pv[8] + Pv[5]) + Pv[7]);
    float s0_1 = (Pv[8] + Pv[7]) + (Pv[5] + Pv[4]);
    float s0_2 = ((Pv[0] + Pv[4]) + (Pv[3] + Pv[6])) + Pv[5];
    float s0_3 = v + Pv[8];
    float s0_4 = v + Pv[7];
    float s0_5 = u + Pv[4];

    // Split accumulators: two independent 3-op chains each.
    float accA = Qv[0] * s1[0];
    float accB = Qv[1] * s1[1];
    accA = fmaf(Qv[2], s1[2], accA);
    accB = fmaf(Qv[3], s1[3], accB);
    accA = fmaf(Qv[4], s1[4], accA);
    accB = fmaf(Qv[5], s1[5], accB);

    float wsA = Qv[0] * s0_0;
    float wsB = Qv[1] * s0_1;
    wsA = fmaf(Qv[2], s0_2, wsA);
    wsB = fmaf(Qv[3], s0_3, wsB);
    wsA = fmaf(Qv[4], s0_4, wsA);
    wsB = fmaf(Qv[5], s0_5, wsB);

    return __fdividef(accA + accB, fmaxf(wsA + wsB, 1e-8f));
}

__global__ void __launch_bounds__(THREADS)
anfis_kernel(const float4* __restrict__ x,
             const float*  __restrict__ c,
             const float*  __restrict__ log_s,
             const float*  __restrict__ conseq,
             float* __restrict__ out,
             int n)
{
    const int t = threadIdx.x;
    const int base = blockIdx.x * TILE + t;
    const bool full = (blockIdx.x * TILE + TILE <= n);

    // Prefetch this thread's rows BEFORE the publish/spin — independent work
    // that hides DRAM latency under the constant-ready wait.
    float4 xv0, xv1;
    if (full) {
        xv0 = __ldg(x + base);
        xv1 = __ldg(x + base + THREADS);
    }

    if (blockIdx.x == 0) {
        // Block 0 computes and publishes the constants.
        if (t < 11) {
            const float KS = 0.8493218002880191f;  // sqrt(0.5 * log2(e))
            float ci  = c[t];
            float sg  = fmaxf(__expf(log_s[t]), 0.001f);
            float ap  = KS / sg;
            g_blob.ab[t] = make_float2(ap, -ci * ap);
        }
        if (t < 32) {
            float v = 0.0f;
            if (t < 30) v = fminf(fmaxf(conseq[GRP_CQ[t]], 0.0f), 100.0f);
            g_blob.cqp[t] = v;
        }
        if (t < 32) __threadfence();   // writers make stores GPU-visible
        __syncthreads();
        if (t == 0) {
            asm volatile("st.release.gpu.global.b32 [%0], %1;"
                         :: "l"(&g_flag), "r"(1) : "memory");
        }
        __syncthreads();
    } else {
        // Other blocks: one thread spins on the acquire flag, then all sync.
        if (t == 0) {
            int f;
            do {
                asm volatile("ld.acquire.gpu.global.b32 %0, [%1];"
                             : "=r"(f) : "l"(&g_flag) : "memory");
            } while (f == 0);
        }
        __syncthreads();
    }

    if (full) {
        float r0 = anfis_row(xv0);
        float r1 = anfis_row(xv1);
        out[base]           = r0;
        out[base + THREADS] = r1;
    } else {
        #pragma unroll
        for (int k = 0; k < ROWS_PER_THREAD; k++) {
            int r = base + k * THREADS;
            if (r < n) {
                float4 xv = __ldg(x + r);
                out[r] = anfis_row(xv);
            }
        }
    }

    // Replay hygiene: last-finishing block resets flag + counter so the next
    // graph replay starts from a clean state. (Next launch cannot begin until
    // all blocks of this one complete — stream order.)
    __syncthreads();
    if (t == 0) {
        unsigned v = atomicAdd(&g_done, 1u);
        if (v == gridDim.x - 1) {
            g_done = 0u;
            asm volatile("st.relaxed.gpu.global.b32 [%0], %1;"
                         :: "l"(&g_flag), "r"(0) : "memory");
        }
    }
}

extern "C" void kernel_launch(void* const* d_in, const int* in_sizes, int n_in,
                              void* d_out, int out_size)
{
    const float* x      = (const float*)d_in[0];
    const float* c      = (const float*)d_in[1];
    const float* log_s  = (const float*)d_in[2];
    const float* conseq = (const float*)d_in[3];
    float* out          = (float*)d_out;

    int n = in_sizes[0] / 4;   // rows
    int blocks = (n + TILE - 1) / TILE;

    anfis_kernel<<<blocks, THREADS>>>((const float4*)x, c, log_s, conseq, out, n);
}

// round 14
// speedup vs baseline: 1.3743x; 1.3743x over previous
#include <cuda_runtime.h>
#include <cuda_bf16.h>

// ANFIS fuzzy inference, batch=2M rows x 4 features.
// out = sum_j(w_j * clip(conseq_j)) / max(sum_j w_j, 1e-8),
// w_j = prod of 4 Gaussian memberships.
//
// Two graph nodes with PDL (validated R10/R12 shell) + PACKED f32x2 body:
//  1) prep kernel writes PRE-REPLICATED constants into the __constant__
//     backing store:
//       ab2[11] : float4 (a',a',b',b')  -> one LDC.128 = both packed operands
//       cq2[15] : float4 (cq,cq,cq',cq') PERMUTED into group order
//     then triggers programmatic launch completion.
//  2) main kernel (ProgrammaticStreamSerialization): prefetch x rows,
//     griddepsync, then evaluate TWO rows per thread as one f32x2 lane pair:
//     memberships/P/Q/weighted/unweighted/accumulators all in
//     fma/mul/add.rn.f32x2 (2x fp32 throughput), constants via vector LDC
//     (zero GPR residency). Sign flips for ex2(-t) ride the idle ALU pipe.
//
// Row math identical algebra to the validated scalar body:
//  pair-product CSE, group factorization over 6 shared Q factors,
//  CSE'd unweighted sums, split accumulators.

namespace {
// Rules grouped by q = (ante2-6)*2 + (ante3-9); p = ante0*3 + (ante1-3).
// Verified against RULE_ANTECEDENTS.
//   group extents: g0: m 0-6, g1: 7-10, g2: 11-15, g3: 16-20, g4: 21-25, g5: 26-29
__device__ constexpr int GRP_P[30]  = {0,3,1,2,8,5,7,  8,7,5,4,  0,4,3,6,5,
                                       0,1,3,2,8,  0,1,3,2,7,  0,1,3,4};
__device__ constexpr int GRP_CQ[30] = {9,13,15,19,23,27,28,  22,24,25,29,
                                       2,11,17,18,20,  4,10,12,14,26,
                                       0,3,6,7,21,  1,5,8,16};
__device__ constexpr int GRP_OF[30] = {0,0,0,0,0,0,0, 1,1,1,1, 2,2,2,2,2,
                                       3,3,3,3,3, 4,4,4,4,4, 5,5,5,5};
__device__ constexpr int DM[11] = {0,0,0,1,1,1,2,2,2,3,3};
}

using u64 = unsigned long long;

// Constant blob, all pre-replicated for f32x2 consumption.
struct CstBlob {
    float4 ab2[11];   // (a', a', b', b') -> LDC.128
    float4 cq2[15];   // (cq[2k],cq[2k],cq[2k+1],cq[2k+1]), permuted order
};
__constant__ CstBlob g_cst;

__device__ __forceinline__ u64 pk2(float lo, float hi) {
    u64 r; asm("mov.b64 %0, {%1, %2};" : "=l"(r) : "f"(lo), "f"(hi)); return r;
}
__device__ __forceinline__ void upk2(u64 v, float& lo, float& hi) {
    asm("mov.b64 {%0, %1}, %2;" : "=f"(lo), "=f"(hi) : "l"(v));
}
__device__ __forceinline__ u64 fma2(u64 a, u64 b, u64 c) {
    u64 d; asm("fma.rn.f32x2 %0, %1, %2, %3;" : "=l"(d) : "l"(a), "l"(b), "l"(c)); return d;
}
__device__ __forceinline__ u64 mul2(u64 a, u64 b) {
    u64 d; asm("mul.rn.f32x2 %0, %1, %2;" : "=l"(d) : "l"(a), "l"(b)); return d;
}
__device__ __forceinline__ u64 add2(u64 a, u64 b) {
    u64 d; asm("add.rn.f32x2 %0, %1, %2;" : "=l"(d) : "l"(a), "l"(b)); return d;
}
// ex2(-t): XOR sign flip (alu pipe) + MUFU.EX2.
__device__ __forceinline__ float ex2neg(float t) {
    float nt = __int_as_float(__float_as_int(t) ^ 0x80000000);
    float r; asm("ex2.approx.ftz.f32 %0, %1;" : "=f"(r) : "f"(nt)); return r;
}
__device__ __forceinline__ float ex2(float t) {
    float r; asm("ex2.approx.ftz.f32 %0, %1;" : "=f"(r) : "f"(t)); return r;
}

// Writes the __constant__ backing store directly, then signals PDL.
__global__ void prep_kernel(const float* __restrict__ c,
                            const float* __restrict__ log_s,
                            const float* __restrict__ conseq,
                            CstBlob* __restrict__ cst)
{
    const int t = threadIdx.x;
    if (t < 11) {
        const float KS = 0.8493218002880191f;  // sqrt(0.5 * log2(e))
        float ci  = c[t];
        float sg  = fmaxf(__expf(log_s[t]), 0.001f);
        float ap  = KS / sg;
        float bp  = -ci * ap;
        cst->ab2[t] = make_float4(ap, ap, bp, bp);
    }
    if (t < 15) {
        float v0 = fminf(fmaxf(conseq[GRP_CQ[2 * t]], 0.0f), 100.0f);
        float v1 = fminf(fmaxf(conseq[GRP_CQ[2 * t + 1]], 0.0f), 100.0f);
        cst->cq2[t] = make_float4(v0, v0, v1, v1);
    }
    __threadfence();
#if __CUDA_ARCH__ >= 900
    cudaTriggerProgrammaticLaunchCompletion();
#endif
}

constexpr int THREADS = 256;
constexpr int ROWS_PER_THREAD = 2;   // one packed f32x2 pair
constexpr int TILE = THREADS * ROWS_PER_THREAD;   // 512 rows/block

// Packed evaluation of a row pair; xp[dim] = (x_lo, x_hi).
__device__ __forceinline__ u64 anfis_pair(const u64 xp[4])
{
    // 11 memberships: LDC.128 + FFMA2 + FMUL2 + 2x(XOR+MUFU) each.
    u64 mu[11];
    #pragma unroll
    for (int i = 0; i < 11; i++) {
        float4 ab = g_cst.ab2[i];
        u64 aa = pk2(ab.x, ab.y);
        u64 bb = pk2(ab.z, ab.w);
        u64 d  = fma2(xp[DM[i]], aa, bb);
        u64 tq = mul2(d, d);
        float tl, th; upk2(tq, tl, th);
        mu[i] = pk2(ex2neg(tl), ex2neg(th));
    }

    // Pair products (packed).
    u64 Pv[9], Qv[6];
    #pragma unroll
    for (int i = 0; i < 3; i++)
        #pragma unroll
        for (int j = 0; j < 3; j++)
            Pv[i * 3 + j] = mul2(mu[i], mu[3 + j]);
    #pragma unroll
    for (int i = 0; i < 3; i++)
        #pragma unroll
        for (int j = 0; j < 2; j++)
            Qv[i * 2 + j] = mul2(mu[6 + i], mu[9 + j]);

    // Weighted group inner sums: 15 LDC.128 deliver 30 replicated cq pairs.
    u64 s1[6];
    #pragma unroll
    for (int g = 0; g < 6; g++) s1[g] = 0ull;

    #pragma unroll
    for (int k = 0; k < 15; k++) {
        float4 C = g_cst.cq2[k];
        u64 c0 = pk2(C.x, C.y);
        u64 c1 = pk2(C.z, C.w);
        const int m0 = 2 * k, m1 = 2 * k + 1;
        s1[GRP_OF[m0]] = fma2(Pv[GRP_P[m0]], c0, s1[GRP_OF[m0]]);
        s1[GRP_OF[m1]] = fma2(Pv[GRP_P[m1]], c1, s1[GRP_OF[m1]]);
    }

    // Unweighted group sums with CSE (16 packed ADDs).
    u64 u = add2(add2(Pv[0], Pv[1]), Pv[3]);   // {0,1,3}
    u64 v = add2(u, Pv[2]);                    // {0,1,2,3}
    u64 s0_0 = add2(v, add2(add2(Pv[8], Pv[5]), Pv[7]));
    u64 s0_1 = add2(add2(Pv[8], Pv[7]), add2(Pv[5], Pv[4]));
    u64 s0_2 = add2(add2(add2(Pv[0], Pv[4]), add2(Pv[3], Pv[6])), Pv[5]);
    u64 s0_3 = add2(v, Pv[8]);
    u64 s0_4 = add2(v, Pv[7]);
    u64 s0_5 = add2(u, Pv[4]);

    // Split accumulators (packed).
    u64 accA = mul2(Qv[0], s1[0]);
    u64 accB = mul2(Qv[1], s1[1]);
    accA = fma2(Qv[2], s1[2], accA);
    accB = fma2(Qv[3], s1[3], accB);
    accA = fma2(Qv[4], s1[4], accA);
    accB = fma2(Qv[5], s1[5], accB);

    u64 wsA = mul2(Qv[0], s0_0);
    u64 wsB = mul2(Qv[1], s0_1);
    wsA = fma2(Qv[2], s0_2, wsA);
    wsB = fma2(Qv[3], s0_3, wsB);
    wsA = fma2(Qv[4], s0_4, wsA);
    wsB = fma2(Qv[5], s0_5, wsB);

    u64 acc  = add2(accA, accB);
    u64 wsum = add2(wsA, wsB);

    float al, ah, wl, wh;
    upk2(acc, al, ah);
    upk2(wsum, wl, wh);
    float rl = __fdividef(al, fmaxf(wl, 1e-8f));
    float rh = __fdividef(ah, fmaxf(wh, 1e-8f));
    return pk2(rl, rh);
}

// Scalar path for the tail tile.
__device__ __forceinline__ float anfis_row_scalar(const float4 xv)
{
    const float xd[4] = {xv.x, xv.y, xv.z, xv.w};
    float mu[11];
    #pragma unroll
    for (int i = 0; i < 11; i++) {
        float4 ab = g_cst.ab2[i];
        float d = fmaf(xd[DM[i]], ab.x, ab.z);
        mu[i] = ex2(-d * d);
    }
    float Pv[9], Qv[6];
    #pragma unroll
    for (int i = 0; i < 3; i++)
        #pragma unroll
        for (int j = 0; j < 3; j++)
            Pv[i * 3 + j] = mu[i] * mu[3 + j];
    #pragma unroll
    for (int i = 0; i < 3; i++)
        #pragma unroll
        for (int j = 0; j < 2; j++)
            Qv[i * 2 + j] = mu[6 + i] * mu[9 + j];

    float s1[6];
    #pragma unroll
    for (int g = 0; g < 6; g++) s1[g] = 0.0f;
    #pragma unroll
    for (int k = 0; k < 15; k++) {
        float4 C = g_cst.cq2[k];
        const int m0 = 2 * k, m1 = 2 * k + 1;
        s1[GRP_OF[m0]] = fmaf(Pv[GRP_P[m0]], C.x, s1[GRP_OF[m0]]);
        s1[GRP_OF[m1]] = fmaf(Pv[GRP_P[m1]], C.z, s1[GRP_OF[m1]]);
    }

    float u = (Pv[0] + Pv[1]) + Pv[3];
    float v = u + Pv[2];
    float s0_0 = v + ((Pv[8] + Pv[5]) + Pv[7]);
    float s0_1 = (Pv[8] + Pv[7]) + (Pv[5] + Pv[4]);
    float s0_2 = ((Pv[0] + Pv[4]) + (Pv[3] + Pv[6])) + Pv[5];
    float s0_3 = v + Pv[8];
    float s0_4 = v + Pv[7];
    float s0_5 = u + Pv[4];

    float accA = Qv[0] * s1[0];
    float accB = Qv[1] * s1[1];
    accA = fmaf(Qv[2], s1[2], accA);
    accB = fmaf(Qv[3], s1[3], accB);
    accA = fmaf(Qv[4], s1[4], accA);
    accB = fmaf(Qv[5], s1[5], accB);

    float wsA = Qv[0] * s0_0;
    float wsB = Qv[1] * s0_1;
    wsA = fmaf(Qv[2], s0_2, wsA);
    wsB = fmaf(Qv[3], s0_3, wsB);
    wsA = fmaf(Qv[4], s0_4, wsA);
    wsB = fmaf(Qv[5], s0_5, wsB);

    return __fdividef(accA + accB, fmaxf(wsA + wsB, 1e-8f));
}

__global__ void __launch_bounds__(THREADS)
anfis_kernel(const float4* __restrict__ x,
             float* __restrict__ out,
             int n)
{
    const int base = blockIdx.x * TILE + threadIdx.x;
    const bool full = (blockIdx.x * TILE + TILE <= n);

    if (full) {
        // Prefetch BEFORE the dependency sync — independent of prep.
        float4 lo = __ldg(x + base);
        float4 hi = __ldg(x + base + THREADS);

#if __CUDA_ARCH__ >= 900
        cudaGridDependencySynchronize();
#endif

        u64 xp[4] = { pk2(lo.x, hi.x), pk2(lo.y, hi.y),
                      pk2(lo.z, hi.z), pk2(lo.w, hi.w) };
        u64 res = anfis_pair(xp);
        float rl, rh; upk2(res, rl, rh);
        out[base]           = rl;
        out[base + THREADS] = rh;
    } else {
#if __CUDA_ARCH__ >= 900
        cudaGridDependencySynchronize();
#endif
        #pragma unroll
        for (int k = 0; k < ROWS_PER_THREAD; k++) {
            int r = base + k * THREADS;
            if (r < n) {
                float4 xv = __ldg(x + r);
                out[r] = anfis_row_scalar(xv);
            }
        }
    }
}

extern "C" void kernel_launch(void* const* d_in, const int* in_sizes, int n_in,
                              void* d_out, int out_size)
{
    const float* x      = (const float*)d_in[0];
    const float* c      = (const float*)d_in[1];
    const float* log_s  = (const float*)d_in[2];
    const float* conseq = (const float*)d_in[3];
    float* out          = (float*)d_out;

    int n = in_sizes[0] / 4;   // rows
    int blocks = (n + TILE - 1) / TILE;

    void* cst_ptr = nullptr;
    cudaGetSymbolAddress(&cst_ptr, g_cst);

    // Node 1: prep (PDL trigger).
    prep_kernel<<<1, 32>>>(c, log_s, conseq, (CstBlob*)cst_ptr);

    // Node 2: main kernel with programmatic dependent launch.
    cudaLaunchConfig_t cfg = {};
    cfg.gridDim  = dim3((unsigned)blocks, 1, 1);
    cfg.blockDim = dim3(THREADS, 1, 1);
    cfg.dynamicSmemBytes = 0;
    cfg.stream = 0;
    cudaLaunchAttribute attrs[1];
    attrs[0].id = cudaLaunchAttributeProgrammaticStreamSerialization;
    attrs[0].val.programmaticStreamSerializationAllowed = 1;
    cfg.attrs = attrs;
    cfg.numAttrs = 1;

    cudaError_t err = cudaLaunchKernelEx(&cfg, anfis_kernel,
                                         (const float4*)x, out, n);
    if (err != cudaSuccess) {
        anfis_kernel<<<blocks, THREADS>>>((const float4*)x, out, n);
    }
}

// round 15
// speedup vs baseline: 1.4447x; 1.0512x over previous
#include <cuda_runtime.h>
#include <cuda_bf16.h>

// ANFIS fuzzy inference, batch=2M rows x 4 features.
// out = sum_j(w_j * clip(conseq_j)) / max(sum_j w_j, 1e-8),
// w_j = prod of 4 Gaussian memberships.
//
// PDL 2-node shell (validated) + packed f32x2 body with TWO interleaved
// pairs per thread (4 rows/thread):
//  - every constant LDC.128 is shared by both pairs (13 LDC/pair, half of R14)
//  - every latency chain has an independent twin -> 2x ILP per warp
//  - 128-thread blocks for finer CTA packing at the higher reg count.
// Constants pre-replicated in __constant__: ab2[11] = (a',a',b',b'),
// cq2[15] = (cq,cq,cq',cq') permuted into group order.

namespace {
// Rules grouped by q = (ante2-6)*2 + (ante3-9); p = ante0*3 + (ante1-3).
// Verified against RULE_ANTECEDENTS.
__device__ constexpr int GRP_P[30]  = {0,3,1,2,8,5,7,  8,7,5,4,  0,4,3,6,5,
                                       0,1,3,2,8,  0,1,3,2,7,  0,1,3,4};
__device__ constexpr int GRP_CQ[30] = {9,13,15,19,23,27,28,  22,24,25,29,
                                       2,11,17,18,20,  4,10,12,14,26,
                                       0,3,6,7,21,  1,5,8,16};
__device__ constexpr int GRP_OF[30] = {0,0,0,0,0,0,0, 1,1,1,1, 2,2,2,2,2,
                                       3,3,3,3,3, 4,4,4,4,4, 5,5,5,5};
__device__ constexpr int DM[11] = {0,0,0,1,1,1,2,2,2,3,3};
}

using u64 = unsigned long long;

struct CstBlob {
    float4 ab2[11];   // (a', a', b', b') -> one LDC.128
    float4 cq2[15];   // (cq[2k],cq[2k],cq[2k+1],cq[2k+1]), permuted order
};
__constant__ CstBlob g_cst;

__device__ __forceinline__ u64 pk2(float lo, float hi) {
    u64 r; asm("mov.b64 %0, {%1, %2};" : "=l"(r) : "f"(lo), "f"(hi)); return r;
}
__device__ __forceinline__ void upk2(u64 v, float& lo, float& hi) {
    asm("mov.b64 {%0, %1}, %2;" : "=f"(lo), "=f"(hi) : "l"(v));
}
__device__ __forceinline__ u64 fma2(u64 a, u64 b, u64 c) {
    u64 d; asm("fma.rn.f32x2 %0, %1, %2, %3;" : "=l"(d) : "l"(a), "l"(b), "l"(c)); return d;
}
__device__ __forceinline__ u64 mul2(u64 a, u64 b) {
    u64 d; asm("mul.rn.f32x2 %0, %1, %2;" : "=l"(d) : "l"(a), "l"(b)); return d;
}
__device__ __forceinline__ u64 add2(u64 a, u64 b) {
    u64 d; asm("add.rn.f32x2 %0, %1, %2;" : "=l"(d) : "l"(a), "l"(b)); return d;
}
__device__ __forceinline__ float ex2neg(float t) {
    float nt = __int_as_float(__float_as_int(t) ^ 0x80000000);
    float r; asm("ex2.approx.ftz.f32 %0, %1;" : "=f"(r) : "f"(nt)); return r;
}
__device__ __forceinline__ float ex2(float t) {
    float r; asm("ex2.approx.ftz.f32 %0, %1;" : "=f"(r) : "f"(t)); return r;
}

__global__ void prep_kernel(const float* __restrict__ c,
                            const float* __restrict__ log_s,
                            const float* __restrict__ conseq,
                            CstBlob* __restrict__ cst)
{
    const int t = threadIdx.x;
    if (t < 11) {
        const float KS = 0.8493218002880191f;  // sqrt(0.5 * log2(e))
        float ci  = c[t];
        float sg  = fmaxf(__expf(log_s[t]), 0.001f);
        float ap  = KS / sg;
        float bp  = -ci * ap;
        cst->ab2[t] = make_float4(ap, ap, bp, bp);
    }
    if (t < 15) {
        float v0 = fminf(fmaxf(conseq[GRP_CQ[2 * t]], 0.0f), 100.0f);
        float v1 = fminf(fmaxf(conseq[GRP_CQ[2 * t + 1]], 0.0f), 100.0f);
        cst->cq2[t] = make_float4(v0, v0, v1, v1);
    }
    __threadfence();
#if __CUDA_ARCH__ >= 900
    cudaTriggerProgrammaticLaunchCompletion();
#endif
}

constexpr int THREADS = 128;
constexpr int ROWS_PER_THREAD = 4;   // two packed f32x2 pairs
constexpr int TILE = THREADS * ROWS_PER_THREAD;   // 512 rows/block

// Two interleaved packed pairs: shared constant loads, doubled ILP.
__device__ __forceinline__ void anfis_pair2(const u64 xp0[4], const u64 xp1[4],
                                            u64& res0, u64& res1)
{
    // Memberships for both pairs; each ab2[i] LDC.128 serves both.
    u64 mu0[11], mu1[11];
    #pragma unroll
    for (int i = 0; i < 11; i++) {
        float4 ab = g_cst.ab2[i];
        u64 aa = pk2(ab.x, ab.y);
        u64 bb = pk2(ab.z, ab.w);
        u64 d0 = fma2(xp0[DM[i]], aa, bb);
        u64 d1 = fma2(xp1[DM[i]], aa, bb);
        u64 t0 = mul2(d0, d0);
        u64 t1 = mul2(d1, d1);
        float a0, b0, a1, b1;
        upk2(t0, a0, b0);
        upk2(t1, a1, b1);
        mu0[i] = pk2(ex2neg(a0), ex2neg(b0));
        mu1[i] = pk2(ex2neg(a1), ex2neg(b1));
    }

    // Pair products for both pairs.
    u64 Pv0[9], Qv0[6], Pv1[9], Qv1[6];
    #pragma unroll
    for (int i = 0; i < 3; i++)
        #pragma unroll
        for (int j = 0; j < 3; j++) {
            Pv0[i * 3 + j] = mul2(mu0[i], mu0[3 + j]);
            Pv1[i * 3 + j] = mul2(mu1[i], mu1[3 + j]);
        }
    #pragma unroll
    for (int i = 0; i < 3; i++)
        #pragma unroll
        for (int j = 0; j < 2; j++) {
            Qv0[i * 2 + j] = mul2(mu0[6 + i], mu0[9 + j]);
            Qv1[i * 2 + j] = mul2(mu1[6 + i], mu1[9 + j]);
        }

    // Weighted group inner sums; each cq2[k] LDC.128 serves 2 rules x 2 pairs.
    u64 s10[6], s11[6];
    #pragma unroll
    for (int g = 0; g < 6; g++) { s10[g] = 0ull; s11[g] = 0ull; }

    #pragma unroll
    for (int k = 0; k < 15; k++) {
        float4 C = g_cst.cq2[k];
        u64 c0 = pk2(C.x, C.y);
        u64 c1 = pk2(C.z, C.w);
        const int m0 = 2 * k, m1 = 2 * k + 1;
        s10[GRP_OF[m0]] = fma2(Pv0[GRP_P[m0]], c0, s10[GRP_OF[m0]]);
        s11[GRP_OF[m0]] = fma2(Pv1[GRP_P[m0]], c0, s11[GRP_OF[m0]]);
        s10[GRP_OF[m1]] = fma2(Pv0[GRP_P[m1]], c1, s10[GRP_OF[m1]]);
        s11[GRP_OF[m1]] = fma2(Pv1[GRP_P[m1]], c1, s11[GRP_OF[m1]]);
    }

    // Unweighted group sums with CSE, both pairs.
    u64 u0 = add2(add2(Pv0[0], Pv0[1]), Pv0[3]);
    u64 v0 = add2(u0, Pv0[2]);
    u64 u1 = add2(add2(Pv1[0], Pv1[1]), Pv1[3]);
    u64 v1 = add2(u1, Pv1[2]);

    u64 s00_0 = add2(v0, add2(add2(Pv0[8], Pv0[5]), Pv0[7]));
    u64 s00_1 = add2(add2(Pv0[8], Pv0[7]), add2(Pv0[5], Pv0[4]));
    u64 s00_2 = add2(add2(add2(Pv0[0], Pv0[4]), add2(Pv0[3], Pv0[6])), Pv0[5]);
    u64 s00_3 = add2(v0, Pv0[8]);
    u64 s00_4 = add2(v0, Pv0[7]);
    u64 s00_5 = add2(u0, Pv0[4]);

    u64 s01_0 = add2(v1, add2(add2(Pv1[8], Pv1[5]), Pv1[7]));
    u64 s01_1 = add2(add2(Pv1[8], Pv1[7]), add2(Pv1[5], Pv1[4]));
    u64 s01_2 = add2(add2(add2(Pv1[0], Pv1[4]), add2(Pv1[3], Pv1[6])), Pv1[5]);
    u64 s01_3 = add2(v1, Pv1[8]);
    u64 s01_4 = add2(v1, Pv1[7]);
    u64 s01_5 = add2(u1, Pv1[4]);

    // Split accumulators, both pairs.
    u64 aA0 = mul2(Qv0[0], s10[0]);
    u64 aB0 = mul2(Qv0[1], s10[1]);
    u64 aA1 = mul2(Qv1[0], s11[0]);
    u64 aB1 = mul2(Qv1[1], s11[1]);
    aA0 = fma2(Qv0[2], s10[2], aA0);  aA1 = fma2(Qv1[2], s11[2], aA1);
    aB0 = fma2(Qv0[3], s10[3], aB0);  aB1 = fma2(Qv1[3], s11[3], aB1);
    aA0 = fma2(Qv0[4], s10[4], aA0);  aA1 = fma2(Qv1[4], s11[4], aA1);
    aB0 = fma2(Qv0[5], s10[5], aB0);  aB1 = fma2(Qv1[5], s11[5], aB1);

    u64 wA0 = mul2(Qv0[0], s00_0);
    u64 wB0 = mul2(Qv0[1], s00_1);
    u64 wA1 = mul2(Qv1[0], s01_0);
    u64 wB1 = mul2(Qv1[1], s01_1);
    wA0 = fma2(Qv0[2], s00_2, wA0);  wA1 = fma2(Qv1[2], s01_2, wA1);
    wB0 = fma2(Qv0[3], s00_3, wB0);  wB1 = fma2(Qv1[3], s01_3, wB1);
    wA0 = fma2(Qv0[4], s00_4, wA0);  wA1 = fma2(Qv1[4], s01_4, wA1);
    wB0 = fma2(Qv0[5], s00_5, wB0);  wB1 = fma2(Qv1[5], s01_5, wB1);

    u64 acc0  = add2(aA0, aB0);
    u64 wsum0 = add2(wA0, wB0);
    u64 acc1  = add2(aA1, aB1);
    u64 wsum1 = add2(wA1, wB1);

    float al0, ah0, wl0, wh0, al1, ah1, wl1, wh1;
    upk2(acc0, al0, ah0);  upk2(wsum0, wl0, wh0);
    upk2(acc1, al1, ah1);  upk2(wsum1, wl1, wh1);
    res0 = pk2(__fdividef(al0, fmaxf(wl0, 1e-8f)),
               __fdividef(ah0, fmaxf(wh0, 1e-8f)));
    res1 = pk2(__fdividef(al1, fmaxf(wl1, 1e-8f)),
               __fdividef(ah1, fmaxf(wh1, 1e-8f)));
}

// Scalar path for the tail tile.
__device__ __forceinline__ float anfis_row_scalar(const float4 xv)
{
    const float xd[4] = {xv.x, xv.y, xv.z, xv.w};
    float mu[11];
    #pragma unroll
    for (int i = 0; i < 11; i++) {
        float4 ab = g_cst.ab2[i];
        float d = fmaf(xd[DM[i]], ab.x, ab.z);
        mu[i] = ex2(-d * d);
    }
    float Pv[9], Qv[6];
    #pragma unroll
    for (int i = 0; i < 3; i++)
        #pragma unroll
        for (int j = 0; j < 3; j++)
            Pv[i * 3 + j] = mu[i] * mu[3 + j];
    #pragma unroll
    for (int i = 0; i < 3; i++)
        #pragma unroll
        for (int j = 0; j < 2; j++)
            Qv[i * 2 + j] = mu[6 + i] * mu[9 + j];

    float s1[6];
    #pragma unroll
    for (int g = 0; g < 6; g++) s1[g] = 0.0f;
    #pragma unroll
    for (int k = 0; k < 15; k++) {
        float4 C = g_cst.cq2[k];
        const int m0 = 2 * k, m1 = 2 * k + 1;
        s1[GRP_OF[m0]] = fmaf(Pv[GRP_P[m0]], C.x, s1[GRP_OF[m0]]);
        s1[GRP_OF[m1]] = fmaf(Pv[GRP_P[m1]], C.z, s1[GRP_OF[m1]]);
    }

    float u = (Pv[0] + Pv[1]) + Pv[3];
    float v = u + Pv[2];
    float s0_0 = v + ((Pv[8] + Pv[5]) + Pv[7]);
    float s0_1 = (Pv[8] + Pv[7]) + (Pv[5] + Pv[4]);
    float s0_2 = ((Pv[0] + Pv[4]) + (Pv[3] + Pv[6])) + Pv[5];
    float s0_3 = v + Pv[8];
    float s0_4 = v + Pv[7];
    float s0_5 = u + Pv[4];

    float accA = Qv[0] * s1[0];
    float accB = Qv[1] * s1[1];
    accA = fmaf(Qv[2], s1[2], accA);
    accB = fmaf(Qv[3], s1[3], accB);
    accA = fmaf(Qv[4], s1[4], accA);
    accB = fmaf(Qv[5], s1[5], accB);

    float wsA = Qv[0] * s0_0;
    float wsB = Qv[1] * s0_1;
    wsA = fmaf(Qv[2], s0_2, wsA);
    wsB = fmaf(Qv[3], s0_3, wsB);
    wsA = fmaf(Qv[4], s0_4, wsA);
    wsB = fmaf(Qv[5], s0_5, wsB);

    return __fdividef(accA + accB, fmaxf(wsA + wsB, 1e-8f));
}

__global__ void __launch_bounds__(THREADS)
anfis_kernel(const float4* __restrict__ x,
             float* __restrict__ out,
             int n)
{
    const int base = blockIdx.x * TILE + threadIdx.x;
    const bool full = (blockIdx.x * TILE + TILE <= n);

    if (full) {
        // Prefetch all 4 rows BEFORE the dependency sync (MLP=4, independent
        // of prep).
        float4 v0 = __ldg(x + base);
        float4 v1 = __ldg(x + base + THREADS);
        float4 v2 = __ldg(x + base + 2 * THREADS);
        float4 v3 = __ldg(x + base + 3 * THREADS);

#if __CUDA_ARCH__ >= 900
        cudaGridDependencySynchronize();
#endif

        u64 xp0[4] = { pk2(v0.x, v1.x), pk2(v0.y, v1.y),
                       pk2(v0.z, v1.z), pk2(v0.w, v1.w) };
        u64 xp1[4] = { pk2(v2.x, v3.x), pk2(v2.y, v3.y),
                       pk2(v2.z, v3.z), pk2(v2.w, v3.w) };

        u64 r0, r1;
        anfis_pair2(xp0, xp1, r0, r1);

        float o0, o1, o2, o3;
        upk2(r0, o0, o1);
        upk2(r1, o2, o3);
        out[base]               = o0;
        out[base + THREADS]     = o1;
        out[base + 2 * THREADS] = o2;
        out[base + 3 * THREADS] = o3;
    } else {
#if __CUDA_ARCH__ >= 900
        cudaGridDependencySynchronize();
#endif
        #pragma unroll
        for (int k = 0; k < ROWS_PER_THREAD; k++) {
            int r = base + k * THREADS;
            if (r < n) {
                float4 xv = __ldg(x + r);
                out[r] = anfis_row_scalar(xv);
            }
        }
    }
}

extern "C" void kernel_launch(void* const* d_in, const int* in_sizes, int n_in,
                              void* d_out, int out_size)
{
    const float* x      = (const float*)d_in[0];
    const float* c      = (const float*)d_in[1];
    const float* log_s  = (const float*)d_in[2];
    const float* conseq = (const float*)d_in[3];
    float* out          = (float*)d_out;

    int n = in_sizes[0] / 4;   // rows
    int blocks = (n + TILE - 1) / TILE;

    void* cst_ptr = nullptr;
    cudaGetSymbolAddress(&cst_ptr, g_cst);

    // Node 1: prep (PDL trigger).
    prep_kernel<<<1, 32>>>(c, log_s, conseq, (CstBlob*)cst_ptr);

    // Node 2: main kernel with programmatic dependent launch.
    cudaLaunchConfig_t cfg = {};
    cfg.gridDim  = dim3((unsigned)blocks, 1, 1);
    cfg.blockDim = dim3(THREADS, 1, 1);
    cfg.dynamicSmemBytes = 0;
    cfg.stream = 0;
    cudaLaunchAttribute attrs[1];
    attrs[0].id = cudaLaunchAttributeProgrammaticStreamSerialization;
    attrs[0].val.programmaticStreamSerializationAllowed = 1;
    cfg.attrs = attrs;
    cfg.numAttrs = 1;

    cudaError_t err = cudaLaunchKernelEx(&cfg, anfis_kernel,
                                         (const float4*)x, out, n);
    if (err != cudaSuccess) {
        anfis_kernel<<<blocks, THREADS>>>((const float4*)x, out, n);
    }
}